// round 8
// baseline (speedup 1.0000x reference)
#include <cuda_runtime.h>
#include <cuda_bf16.h>

// NeuSSampler inverse-CDF importance sampling — v7 bitmap rank/select.
// weights [R,128,1] f32, existing_bins [R,129] f32, nears [R,1], fars [R,1]
// -> out [R,65] f32.  One warp per ray, zero shared memory.
//
// Owner lookup for all 65 queries is O(1) warp ops (ballot + 2x redux.or
// + popc + __fns) instead of per-query shuffle ladders:
//   m0_L = first query index claimed by lane L's CDF chunk (local FMA);
//   nonempty chunks have strictly increasing starts -> 65-bit start bitmap M
//   and lane bitmap N; owner(j) = fns(N, popc(M & bits<=j)).
// Value fetch: 10 shfl/round for 2 rounds; j=64 computed locally by its
// (warp-uniform) owner lane with zero shuffles.

#define S_SAMP 128
#define NB 65
#define HIST_PAD 1e-5f
#define EPS_V 1e-5f
#define WARPS_PER_BLOCK 8
#define NTHREADS (WARPS_PER_BLOCK * 32)
#define INV_NB (1.0f / 65.0f)
#define FULL 0xffffffffu

__global__ __launch_bounds__(NTHREADS)
void neus_sampler_kernel(const float* __restrict__ weights,
                         const float* __restrict__ ebins,
                         const float* __restrict__ nears,
                         const float* __restrict__ fars,
                         float* __restrict__ out,
                         int R)
{
    const int warp = threadIdx.x >> 5;
    const int lane = threadIdx.x & 31;
    const int ray  = blockIdx.x * WARPS_PER_BLOCK + warp;
    if (ray >= R) return;

    // ---- A. raw cumsum + warp scan (512B-stride rows: float4 ok) ----
    const float4 wv = *reinterpret_cast<const float4*>(
        weights + (size_t)ray * S_SAMP + lane * 4);
    const float l0 = wv.x;
    const float l1 = l0 + wv.y;
    const float l2 = l1 + wv.z;
    const float l3 = l2 + wv.w;

    float pre = l3;
    #pragma unroll
    for (int off = 1; off < 32; off <<= 1) {
        float v = __shfl_up_sync(FULL, pre, off);
        if (lane >= off) pre += v;
    }
    const float total_raw = __shfl_sync(FULL, pre, 31);
    const float excl      = pre - l3;

    const float total_wp = total_raw + (float)S_SAMP * HIST_PAD;
    const float padding  = fmaxf(0.0f, EPS_V - total_wp);
    const float inv_wsum = __fdividef(1.0f, total_wp + padding);
    const float step     = HIST_PAD + padding * (1.0f / (float)S_SAMP);

    const int k  = lane * 4;
    const float kf = (float)k;
    const float c0 = fmaf(kf,        step, excl     ) * inv_wsum;
    const float c1 = fmaf(kf + 1.0f, step, excl + l0) * inv_wsum;
    const float c2 = fmaf(kf + 2.0f, step, excl + l1) * inv_wsum;
    const float c3 = fmaf(kf + 3.0f, step, excl + l2) * inv_wsum;
    const float c4 = fmaf(kf + 4.0f, step, excl + l3) * inv_wsum;

    // ---- B. bin edges (516B row stride -> scalar loads) ----
    const float* eb = ebins + (size_t)ray * (S_SAMP + 1) + k;
    const float b0 = __ldg(eb + 0);
    const float b1 = __ldg(eb + 1);
    const float b2 = __ldg(eb + 2);
    const float b3 = __ldg(eb + 3);
    float b4 = __shfl_down_sync(FULL, b0, 1);
    if (lane == 31) b4 = __ldg(eb + 4);   // ebins[ray][128]

    // ---- C. owner bitmaps (once per ray) ----
    const int m0 = __float2int_rd(fmaf(65.0f, c0, 0.5f));   // chunk start
    int m_next = __shfl_down_sync(FULL, m0, 1);
    if (lane == 31) m_next = NB;                            // sentinel
    const bool nonempty = (m0 < m_next);

    const unsigned N    = __ballot_sync(FULL, nonempty);
    const unsigned Mlo  = __reduce_or_sync(FULL,
        (nonempty && m0 < 32) ? (1u << m0) : 0u);
    const unsigned Mhi  = __reduce_or_sync(FULL,
        (nonempty && m0 >= 32 && m0 < 64) ? (1u << (m0 - 32)) : 0u);
    const unsigned has64 = __ballot_sync(FULL, nonempty && m0 == 64);
    const int poplo = __popc(Mlo);

    const float nearv = nears[ray];
    const float dfn   = fars[ray] - nearv;
    float* orow = out + (size_t)ray * NB;

    // ---- D. round 0: j = lane (0..31) ----
    {
        const int cnt = __popc(Mlo & (0xffffffffu >> (31 - lane)));
        const int pos = (int)__fns(N, 0, cnt);
        const float u = ((float)lane + 0.5f) * INV_NB;

        const float C0 = __shfl_sync(FULL, c0, pos);
        const float C1 = __shfl_sync(FULL, c1, pos);
        const float C2 = __shfl_sync(FULL, c2, pos);
        const float C3 = __shfl_sync(FULL, c3, pos);
        const float C4 = __shfl_sync(FULL, c4, pos);
        const float B0 = __shfl_sync(FULL, b0, pos);
        const float B1 = __shfl_sync(FULL, b1, pos);
        const float B2 = __shfl_sync(FULL, b2, pos);
        const float B3 = __shfl_sync(FULL, b3, pos);
        const float B4 = __shfl_sync(FULL, b4, pos);

        float clo = C0, chi = C1, blo = B0, bhi = B1;
        if (C1 <= u) { clo = C1; chi = C2; blo = B1; bhi = B2; }
        if (C2 <= u) { clo = C2; chi = C3; blo = B2; bhi = B3; }
        if (C3 <= u) { clo = C3; chi = C4; blo = B3; bhi = B4; }

        const float t  = (u - clo) * __fdividef(1.0f, chi - clo);
        const float bb = fmaf(t, bhi - blo, blo);
        orow[lane] = fmaf(bb, dfn, nearv);
    }

    // ---- E. round 1: j = lane + 32 (32..63) ----
    {
        const int j   = lane + 32;
        const int cnt = poplo + __popc(Mhi & (0xffffffffu >> (63 - j)));
        const int pos = (int)__fns(N, 0, cnt);
        const float u = ((float)j + 0.5f) * INV_NB;

        const float C0 = __shfl_sync(FULL, c0, pos);
        const float C1 = __shfl_sync(FULL, c1, pos);
        const float C2 = __shfl_sync(FULL, c2, pos);
        const float C3 = __shfl_sync(FULL, c3, pos);
        const float C4 = __shfl_sync(FULL, c4, pos);
        const float B0 = __shfl_sync(FULL, b0, pos);
        const float B1 = __shfl_sync(FULL, b1, pos);
        const float B2 = __shfl_sync(FULL, b2, pos);
        const float B3 = __shfl_sync(FULL, b3, pos);
        const float B4 = __shfl_sync(FULL, b4, pos);

        float clo = C0, chi = C1, blo = B0, bhi = B1;
        if (C1 <= u) { clo = C1; chi = C2; blo = B1; bhi = B2; }
        if (C2 <= u) { clo = C2; chi = C3; blo = B2; bhi = B3; }
        if (C3 <= u) { clo = C3; chi = C4; blo = B3; bhi = B4; }

        const float t  = (u - clo) * __fdividef(1.0f, chi - clo);
        const float bb = fmaf(t, bhi - blo, blo);
        orow[j] = fmaf(bb, dfn, nearv);
    }

    // ---- F. j = 64: warp-uniform owner computes locally, no shuffles ----
    {
        const int cnt64 = poplo + __popc(Mhi) + (has64 ? 1 : 0);
        const int pos64 = (int)__fns(N, 0, cnt64);
        if (lane == pos64) {
            const float u = 64.5f * INV_NB;
            float clo = c0, chi = c1, blo = b0, bhi = b1;
            if (c1 <= u) { clo = c1; chi = c2; blo = b1; bhi = b2; }
            if (c2 <= u) { clo = c2; chi = c3; blo = b2; bhi = b3; }
            if (c3 <= u) { clo = c3; chi = c4; blo = b3; bhi = b4; }
            const float t  = (u - clo) * __fdividef(1.0f, chi - clo);
            const float bb = fmaf(t, bhi - blo, blo);
            orow[64] = fmaf(bb, dfn, nearv);
        }
    }
}

extern "C" void kernel_launch(void* const* d_in, const int* in_sizes, int n_in,
                              void* d_out, int out_size) {
    const float* weights = (const float*)d_in[0];
    const float* ebins   = (const float*)d_in[1];
    const float* nears   = (const float*)d_in[2];
    const float* fars    = (const float*)d_in[3];
    float* out = (float*)d_out;

    const int R = in_sizes[2];  // nears has R elements
    const int grid = (R + WARPS_PER_BLOCK - 1) / WARPS_PER_BLOCK;
    neus_sampler_kernel<<<grid, NTHREADS>>>(weights, ebins, nears, fars, out, R);
}

// round 9
// speedup vs baseline: 1.2876x; 1.2876x over previous
#include <cuda_runtime.h>
#include <cuda_bf16.h>

// NeuSSampler inverse-CDF importance sampling — v8 "lean ladder".
// weights [R,128,1] f32, existing_bins [R,129] f32, nears [R,1], fars [R,1]
// -> out [R,65] f32.  One warp per ray, zero shared memory.
//
// Per query: 5-step shfl ladder over sorted chunk tops c0 (tracking clo for
// free), 4 shfl fetch C1..C4, compare-chain sub-segment select, then blo/bhi
// via 2 scalar LDGs from the (L1-resident) ebins row. j=64 owner found with
// one ballot+clz; owner lane computes from its own registers.

#define S_SAMP 128
#define NB 65
#define HIST_PAD 1e-5f
#define EPS_V 1e-5f
#define WARPS_PER_BLOCK 8
#define NTHREADS (WARPS_PER_BLOCK * 32)
#define INV_NB (1.0f / 65.0f)
#define FULL 0xffffffffu

__global__ __launch_bounds__(NTHREADS)
void neus_sampler_kernel(const float* __restrict__ weights,
                         const float* __restrict__ ebins,
                         const float* __restrict__ nears,
                         const float* __restrict__ fars,
                         float* __restrict__ out,
                         int R)
{
    const int warp = threadIdx.x >> 5;
    const int lane = threadIdx.x & 31;
    const int ray  = blockIdx.x * WARPS_PER_BLOCK + warp;
    if (ray >= R) return;

    // ---- A. raw cumsum + warp scan (512B-stride rows: float4 ok) ----
    const float4 wv = *reinterpret_cast<const float4*>(
        weights + (size_t)ray * S_SAMP + lane * 4);
    const float l0 = wv.x;
    const float l1 = l0 + wv.y;
    const float l2 = l1 + wv.z;
    const float l3 = l2 + wv.w;

    float pre = l3;
    #pragma unroll
    for (int off = 1; off < 32; off <<= 1) {
        float v = __shfl_up_sync(FULL, pre, off);
        if (lane >= off) pre += v;
    }
    const float total_raw = __shfl_sync(FULL, pre, 31);
    const float excl      = pre - l3;

    const float total_wp = total_raw + (float)S_SAMP * HIST_PAD;
    const float padding  = fmaxf(0.0f, EPS_V - total_wp);
    const float inv_wsum = __fdividef(1.0f, total_wp + padding);
    const float step     = HIST_PAD + padding * (1.0f / (float)S_SAMP);

    const int k  = lane * 4;
    const float kf = (float)k;
    const float c0 = fmaf(kf,        step, excl     ) * inv_wsum;
    const float c1 = fmaf(kf + 1.0f, step, excl + l0) * inv_wsum;
    const float c2 = fmaf(kf + 2.0f, step, excl + l1) * inv_wsum;
    const float c3 = fmaf(kf + 3.0f, step, excl + l2) * inv_wsum;
    const float c4 = fmaf(kf + 4.0f, step, excl + l3) * inv_wsum;

    const float* ebrow = ebins + (size_t)ray * (S_SAMP + 1);
    const float nearv = nears[ray];
    const float dfn   = fars[ray] - nearv;
    float* orow = out + (size_t)ray * NB;

    // ---- B. two dense rounds: j = lane, j = lane + 32 ----
    #pragma unroll
    for (int q = 0; q < 2; q++) {
        const int j   = lane + 32 * q;
        const float u = ((float)j + 0.5f) * INV_NB;

        // 5-step ladder over chunk tops, tracking clo = c0[pos]
        int pos = 0;
        float clo = 0.0f;          // c0 of lane 0 is exactly 0
        float cv;
        cv = __shfl_sync(FULL, c0, 16);      if (cv <= u) { pos = 16;  clo = cv; }
        cv = __shfl_sync(FULL, c0, pos + 8); if (cv <= u) { pos += 8;  clo = cv; }
        cv = __shfl_sync(FULL, c0, pos + 4); if (cv <= u) { pos += 4;  clo = cv; }
        cv = __shfl_sync(FULL, c0, pos + 2); if (cv <= u) { pos += 2;  clo = cv; }
        cv = __shfl_sync(FULL, c0, pos + 1); if (cv <= u) { pos += 1;  clo = cv; }

        // fetch owner's intra-chunk cdf values
        const float C1 = __shfl_sync(FULL, c1, pos);
        const float C2 = __shfl_sync(FULL, c2, pos);
        const float C3 = __shfl_sync(FULL, c3, pos);
        const float C4 = __shfl_sync(FULL, c4, pos);

        int r = 0; float chi = C1;
        if (C1 <= u) { r = 1; clo = C1; chi = C2; }
        if (C2 <= u) { r = 2; clo = C2; chi = C3; }
        if (C3 <= u) { r = 3; clo = C3; chi = C4; }

        const int idx   = pos * 4 + r;          // cdf[idx] <= u < cdf[idx+1]
        const float blo = __ldg(ebrow + idx);
        const float bhi = __ldg(ebrow + idx + 1);

        const float t  = (u - clo) * __fdividef(1.0f, chi - clo);
        const float bb = fmaf(t, bhi - blo, blo);
        orow[j] = fmaf(bb, dfn, nearv);
    }

    // ---- C. j = 64: owner lane via ballot, local computation ----
    {
        const float u = 64.5f * INV_NB;
        const unsigned msk = __ballot_sync(FULL, c0 <= u);  // lane0 always set
        const int pos = 31 - __clz(msk);
        if (lane == pos) {
            int r = 0; float clo = c0, chi = c1;
            if (c1 <= u) { r = 1; clo = c1; chi = c2; }
            if (c2 <= u) { r = 2; clo = c2; chi = c3; }
            if (c3 <= u) { r = 3; clo = c3; chi = c4; }
            const int idx   = lane * 4 + r;
            const float blo = __ldg(ebrow + idx);
            const float bhi = __ldg(ebrow + idx + 1);
            const float t  = (u - clo) * __fdividef(1.0f, chi - clo);
            const float bb = fmaf(t, bhi - blo, blo);
            orow[64] = fmaf(bb, dfn, nearv);
        }
    }
}

extern "C" void kernel_launch(void* const* d_in, const int* in_sizes, int n_in,
                              void* d_out, int out_size) {
    const float* weights = (const float*)d_in[0];
    const float* ebins   = (const float*)d_in[1];
    const float* nears   = (const float*)d_in[2];
    const float* fars    = (const float*)d_in[3];
    float* out = (float*)d_out;

    const int R = in_sizes[2];  // nears has R elements
    const int grid = (R + WARPS_PER_BLOCK - 1) / WARPS_PER_BLOCK;
    neus_sampler_kernel<<<grid, NTHREADS>>>(weights, ebins, nears, fars, out, R);
}

// round 10
// speedup vs baseline: 1.2965x; 1.0069x over previous
#include <cuda_runtime.h>
#include <cuda_bf16.h>

// NeuSSampler inverse-CDF importance sampling — v9 "lean ladder + overlap".
// weights [R,128,1] f32, existing_bins [R,129] f32, nears [R,1], fars [R,1]
// -> out [R,65] f32.  One warp per ray, zero shared memory.
//
// v8 algorithm (shfl ladder over chunk tops + 4-shfl intra fetch + L1 bin
// LDGs) with latency restructuring:
//   * ebins row prefetched into L1 at kernel entry (overlaps scan latency,
//     turns query-phase LDGs into L1 hits)
//   * the two query rounds' shfl ladders are hand-interleaved (one shared
//     probe + pairwise-independent steps) to halve dependent-chain latency.

#define S_SAMP 128
#define NB 65
#define HIST_PAD 1e-5f
#define EPS_V 1e-5f
#define WARPS_PER_BLOCK 8
#define NTHREADS (WARPS_PER_BLOCK * 32)
#define INV_NB (1.0f / 65.0f)
#define FULL 0xffffffffu

__global__ __launch_bounds__(NTHREADS)
void neus_sampler_kernel(const float* __restrict__ weights,
                         const float* __restrict__ ebins,
                         const float* __restrict__ nears,
                         const float* __restrict__ fars,
                         float* __restrict__ out,
                         int R)
{
    const int warp = threadIdx.x >> 5;
    const int lane = threadIdx.x & 31;
    const int ray  = blockIdx.x * WARPS_PER_BLOCK + warp;
    if (ray >= R) return;

    // ---- A0. start all global traffic early ----
    const float* ebrow = ebins + (size_t)ray * (S_SAMP + 1);
    if (lane < 5) {   // 5 probes, 128B apart, cover the whole 516B row
        asm volatile("prefetch.global.L1 [%0];" :: "l"(ebrow + lane * 32));
    }
    const float nearv = nears[ray];
    const float farv  = fars[ray];

    const float4 wv = *reinterpret_cast<const float4*>(
        weights + (size_t)ray * S_SAMP + lane * 4);
    const float l0 = wv.x;
    const float l1 = l0 + wv.y;
    const float l2 = l1 + wv.z;
    const float l3 = l2 + wv.w;

    // ---- A1. warp inclusive scan over chunk sums ----
    float pre = l3;
    #pragma unroll
    for (int off = 1; off < 32; off <<= 1) {
        float v = __shfl_up_sync(FULL, pre, off);
        if (lane >= off) pre += v;
    }
    const float total_raw = __shfl_sync(FULL, pre, 31);
    const float excl      = pre - l3;

    const float total_wp = total_raw + (float)S_SAMP * HIST_PAD;
    const float padding  = fmaxf(0.0f, EPS_V - total_wp);
    const float inv_wsum = __fdividef(1.0f, total_wp + padding);
    const float step     = HIST_PAD + padding * (1.0f / (float)S_SAMP);

    const int k  = lane * 4;
    const float kf = (float)k;
    const float c0 = fmaf(kf,        step, excl     ) * inv_wsum;
    const float c1 = fmaf(kf + 1.0f, step, excl + l0) * inv_wsum;
    const float c2 = fmaf(kf + 2.0f, step, excl + l1) * inv_wsum;
    const float c3 = fmaf(kf + 3.0f, step, excl + l2) * inv_wsum;
    const float c4 = fmaf(kf + 4.0f, step, excl + l3) * inv_wsum;

    const float dfn = farv - nearv;
    float* orow = out + (size_t)ray * NB;

    // ---- B. dual interleaved ladder: j0 = lane, j1 = lane + 32 ----
    const float u0 = ((float)lane + 0.5f)  * INV_NB;
    const float u1 = ((float)lane + 32.5f) * INV_NB;

    int p0 = 0, p1 = 0;
    float lo0 = 0.0f, lo1 = 0.0f;        // c0 of lane 0 is exactly 0

    {   // step 16 — probe is identical for both rounds
        const float cs = __shfl_sync(FULL, c0, 16);
        if (cs <= u0) { p0 = 16; lo0 = cs; }
        if (cs <= u1) { p1 = 16; lo1 = cs; }
    }
    #pragma unroll
    for (int st = 8; st >= 1; st >>= 1) {
        const float a0 = __shfl_sync(FULL, c0, p0 + st);
        const float a1 = __shfl_sync(FULL, c0, p1 + st);
        if (a0 <= u0) { p0 += st; lo0 = a0; }
        if (a1 <= u1) { p1 += st; lo1 = a1; }
    }

    // intra-chunk cdf values for both owners (interleaved, independent)
    const float C1a = __shfl_sync(FULL, c1, p0);
    const float C1b = __shfl_sync(FULL, c1, p1);
    const float C2a = __shfl_sync(FULL, c2, p0);
    const float C2b = __shfl_sync(FULL, c2, p1);
    const float C3a = __shfl_sync(FULL, c3, p0);
    const float C3b = __shfl_sync(FULL, c3, p1);
    const float C4a = __shfl_sync(FULL, c4, p0);
    const float C4b = __shfl_sync(FULL, c4, p1);

    int r0 = 0; float hi0 = C1a;
    if (C1a <= u0) { r0 = 1; lo0 = C1a; hi0 = C2a; }
    if (C2a <= u0) { r0 = 2; lo0 = C2a; hi0 = C3a; }
    if (C3a <= u0) { r0 = 3; lo0 = C3a; hi0 = C4a; }

    int r1 = 0; float hi1 = C1b;
    if (C1b <= u1) { r1 = 1; lo1 = C1b; hi1 = C2b; }
    if (C2b <= u1) { r1 = 2; lo1 = C2b; hi1 = C3b; }
    if (C3b <= u1) { r1 = 3; lo1 = C3b; hi1 = C4b; }

    const int i0 = p0 * 4 + r0;
    const int i1 = p1 * 4 + r1;
    const float blo0 = __ldg(ebrow + i0);       // L1 hits (prefetched)
    const float bhi0 = __ldg(ebrow + i0 + 1);
    const float blo1 = __ldg(ebrow + i1);
    const float bhi1 = __ldg(ebrow + i1 + 1);

    const float t0  = (u0 - lo0) * __fdividef(1.0f, hi0 - lo0);
    const float t1  = (u1 - lo1) * __fdividef(1.0f, hi1 - lo1);
    const float bb0 = fmaf(t0, bhi0 - blo0, blo0);
    const float bb1 = fmaf(t1, bhi1 - blo1, blo1);
    orow[lane]      = fmaf(bb0, dfn, nearv);
    orow[lane + 32] = fmaf(bb1, dfn, nearv);

    // ---- C. j = 64: owner lane via ballot, computes locally ----
    {
        const float u = 64.5f * INV_NB;
        const unsigned msk = __ballot_sync(FULL, c0 <= u);  // lane0 always set
        const int pos = 31 - __clz(msk);
        if (lane == pos) {
            int r = 0; float clo = c0, chi = c1;
            if (c1 <= u) { r = 1; clo = c1; chi = c2; }
            if (c2 <= u) { r = 2; clo = c2; chi = c3; }
            if (c3 <= u) { r = 3; clo = c3; chi = c4; }
            const int idx   = lane * 4 + r;
            const float blo = __ldg(ebrow + idx);
            const float bhi = __ldg(ebrow + idx + 1);
            const float t  = (u - clo) * __fdividef(1.0f, chi - clo);
            const float bb = fmaf(t, bhi - blo, blo);
            orow[64] = fmaf(bb, dfn, nearv);
        }
    }
}

extern "C" void kernel_launch(void* const* d_in, const int* in_sizes, int n_in,
                              void* d_out, int out_size) {
    const float* weights = (const float*)d_in[0];
    const float* ebins   = (const float*)d_in[1];
    const float* nears   = (const float*)d_in[2];
    const float* fars    = (const float*)d_in[3];
    float* out = (float*)d_out;

    const int R = in_sizes[2];  // nears has R elements
    const int grid = (R + WARPS_PER_BLOCK - 1) / WARPS_PER_BLOCK;
    neus_sampler_kernel<<<grid, NTHREADS>>>(weights, ebins, nears, fars, out, R);
}